// round 13
// baseline (speedup 1.0000x reference)
#include <cuda_runtime.h>
#include <cuda_fp16.h>
#include <stdint.h>
#include <math.h>

#define N_TOK 4096
#define DIM   1024
#define HID   4096
#define NEXP  8
#define NSLOT 8192
#define SLOT_PAD (NSLOT + 128)
#define MAX_TILES 72

// ---------------- scratch (__device__ globals only) ----------------
__device__ int g_offsets[NEXP + 1];
__device__ int g_tg_e[N_TOK * 2];
__device__ float g_tg_w[N_TOK * 2];
__device__ int g_slot_token[NSLOT];
__device__ float g_slot_w[NSLOT];
__device__ int g_tile_e[MAX_TILES];
__device__ int g_tile_bm[MAX_TILES];
__device__ int g_ntiles;

__device__ __align__(16) __half g_Xg[(size_t)SLOT_PAD * DIM];
__device__ __align__(16) __half g_Hg[(size_t)SLOT_PAD * HID];
__device__ __align__(16) __half g_W1t[(size_t)NEXP * HID * DIM]; // [e][h][d]
__device__ __align__(16) __half g_W2t[(size_t)NEXP * DIM * HID]; // [e][d][h]

// ---------------- helpers ----------------
__device__ __forceinline__ uint32_t smem_u32(const void* p) {
    uint32_t a;
    asm("{ .reg .u64 t; cvta.to.shared.u64 t, %1; cvt.u32.u64 %0, t; }" : "=r"(a) : "l"(p));
    return a;
}
__device__ __forceinline__ uint32_t pack2h(__half a, __half b) {
    return (uint32_t)__half_as_ushort(a) | ((uint32_t)__half_as_ushort(b) << 16);
}
__device__ __forceinline__ void cp16(uint32_t dst, const void* src) {
    asm volatile("cp.async.cg.shared.global [%0], [%1], 16;" :: "r"(dst), "l"(src));
}
#define CP_COMMIT() asm volatile("cp.async.commit_group;" ::: "memory")
#define CP_WAIT2()  asm volatile("cp.async.wait_group 2;" ::: "memory")

__device__ __forceinline__ void ldm4(uint32_t* r, uint32_t addr) {
    asm volatile("ldmatrix.sync.aligned.m8n8.x4.shared.b16 {%0,%1,%2,%3}, [%4];"
                 : "=r"(r[0]), "=r"(r[1]), "=r"(r[2]), "=r"(r[3]) : "r"(addr));
}
__device__ __forceinline__ void mma16816(float* c, const uint32_t* a, const uint32_t* b) {
    asm volatile("mma.sync.aligned.m16n8k16.row.col.f32.f16.f16.f32 "
                 "{%0,%1,%2,%3}, {%4,%5,%6,%7}, {%8,%9}, {%0,%1,%2,%3};"
                 : "+f"(c[0]), "+f"(c[1]), "+f"(c[2]), "+f"(c[3])
                 : "r"(a[0]), "r"(a[1]), "r"(a[2]), "r"(a[3]), "r"(b[0]), "r"(b[1]));
}

// ---------------- 0) zero out ----------------
__global__ void k_zero_out(float* __restrict__ out) {
    int i = blockIdx.x * blockDim.x + threadIdx.x;
    ((float4*)out)[i] = make_float4(0.f, 0.f, 0.f, 0.f);
}

// ---------------- 1) gating ----------------
__global__ void k_gate(const float* __restrict__ x, const float* __restrict__ Wg,
                       const float* __restrict__ bg) {
    int wid = threadIdx.x >> 5, lane = threadIdx.x & 31;
    int n = blockIdx.x * 8 + wid;
    float acc[8] = {0,0,0,0,0,0,0,0};
    const float4* wg4 = (const float4*)Wg;
    for (int k = lane; k < DIM; k += 32) {
        float xv = x[(size_t)n * DIM + k];
        float4 w0 = wg4[k * 2], w1 = wg4[k * 2 + 1];
        acc[0] = fmaf(xv, w0.x, acc[0]); acc[1] = fmaf(xv, w0.y, acc[1]);
        acc[2] = fmaf(xv, w0.z, acc[2]); acc[3] = fmaf(xv, w0.w, acc[3]);
        acc[4] = fmaf(xv, w1.x, acc[4]); acc[5] = fmaf(xv, w1.y, acc[5]);
        acc[6] = fmaf(xv, w1.z, acc[6]); acc[7] = fmaf(xv, w1.w, acc[7]);
    }
    #pragma unroll
    for (int e = 0; e < 8; e++)
        #pragma unroll
        for (int off = 16; off; off >>= 1)
            acc[e] += __shfl_down_sync(0xffffffffu, acc[e], off);
    if (lane == 0) {
        float s[8];
        #pragma unroll
        for (int e = 0; e < 8; e++) s[e] = acc[e] + bg[e];
        int e0 = 0; float s0 = s[0];
        #pragma unroll
        for (int e = 1; e < 8; e++) if (s[e] > s0) { s0 = s[e]; e0 = e; }
        int e1 = -1; float s1 = -3.0e38f;
        #pragma unroll
        for (int e = 0; e < 8; e++) if (e != e0 && s[e] > s1) { s1 = s[e]; e1 = e; }
        float t = expf(s1 - s0);
        g_tg_e[n * 2] = e0; g_tg_e[n * 2 + 1] = e1;
        g_tg_w[n * 2] = 1.f / (1.f + t); g_tg_w[n * 2 + 1] = t / (1.f + t);
    }
}

// ---------------- 1b) fused scan + tile map + scatter (single block) ----------------
__global__ void k_scanscatter() {
    __shared__ int cnt[NEXP], off[NEXP], cur[NEXP];
    int t = threadIdx.x;
    if (t < NEXP) cnt[t] = 0;
    __syncthreads();
    for (int i = t; i < N_TOK * 2; i += 256) atomicAdd(&cnt[g_tg_e[i]], 1);
    __syncthreads();
    if (t == 0) {
        int o = 0, tt = 0;
        for (int e = 0; e < NEXP; e++) {
            off[e] = o; g_offsets[e] = o; cur[e] = 0;
            int c = cnt[e];
            for (int bm = 0; bm * 128 < c; bm++) { g_tile_e[tt] = e; g_tile_bm[tt] = bm; tt++; }
            o += c;
        }
        g_offsets[NEXP] = o;
        g_ntiles = tt;
    }
    __syncthreads();
    for (int i = t; i < N_TOK * 2; i += 256) {
        int e = g_tg_e[i];
        int slot = off[e] + atomicAdd(&cur[e], 1);
        g_slot_token[slot] = i >> 1;
        g_slot_w[slot] = g_tg_w[i];
    }
}

// ---------------- 2) gather x -> fp16 ----------------
__global__ void k_gather(const float* __restrict__ x) {
    int s = blockIdx.x, t = threadIdx.x;
    int n = g_slot_token[s];
    const float4* xr = (const float4*)(x + (size_t)n * DIM);
    float4 a = xr[t * 2], b = xr[t * 2 + 1];
    uint32_t p[4];
    p[0] = pack2h(__float2half_rn(a.x), __float2half_rn(a.y));
    p[1] = pack2h(__float2half_rn(a.z), __float2half_rn(a.w));
    p[2] = pack2h(__float2half_rn(b.x), __float2half_rn(b.y));
    p[3] = pack2h(__float2half_rn(b.z), __float2half_rn(b.w));
    *(uint4*)(g_Xg + (size_t)s * DIM + t * 8) = *(uint4*)p;
}

// ---------------- 3) weight transpose to fp16: in[e][R][C] -> out[e][C][R] ----------------
__global__ void k_prep_w(const float* __restrict__ in, int R, int C, int which) {
    __half* o = which ? g_W2t : g_W1t;
    __shared__ float tile[32][65];   // [c][r]
    int e = blockIdx.z;
    int r0 = blockIdx.y * 64, c0 = blockIdx.x * 32;
    int tx = threadIdx.x, ty = threadIdx.y;   // 32 x 8
    const float* ip = in + (size_t)e * R * C;
    #pragma unroll
    for (int j = 0; j < 64; j += 8)
        tile[tx][ty + j] = ip[(size_t)(r0 + ty + j) * C + c0 + tx];
    __syncthreads();
    size_t ob = (size_t)e * R * C;
    int t = ty * 32 + tx;
    #pragma unroll
    for (int i = t; i < 1024; i += 256) {
        int c = i >> 5;            // 0..31
        int rp = (i & 31) * 2;     // 0..62
        uint32_t v = pack2h(__float2half_rn(tile[c][rp]),
                            __float2half_rn(tile[c][rp + 1]));
        *(uint32_t*)(o + ob + (size_t)(c0 + c) * R + r0 + rp) = v;
    }
}

// ---------------- 4) grouped GEMM: 128x128x32 CTA, 4 warps 64x64, 4-stage ----------------
// KSTRIDE = row stride of A/B (full K), KLEN = K-extent this CTA reduces (k-split slices
// selected by blockIdx.z; GEMM2 uses 4 slices with atomic partial accumulation into out).
#define ROWB   80
#define T_A    0
#define T_B    10240
#define STAGEB 20480
#define NSTAGE 4
#define SMEM_BYTES (STAGEB * NSTAGE)

template <int KSTRIDE, int KLEN, bool FFN1>
__global__ void __launch_bounds__(128) k_gemm(const float* __restrict__ bias_all,
                                              float* __restrict__ out) {
    constexpr int NTOT = FFN1 ? HID : DIM;
    constexpr int NCHUNK = KLEN / 32;
    extern __shared__ char sm[];
    uint32_t smb = smem_u32(sm);

    int tile = blockIdx.y;
    if (tile >= g_ntiles) return;
    int e = g_tile_e[tile];
    int bm = g_tile_bm[tile];
    int off_e = g_offsets[e];
    int cnt = g_offsets[e + 1] - off_e;
    int n_base = blockIdx.x * 128;
    int ks = blockIdx.z;               // k-split slice
    int k_base = ks * KLEN;
    int slot0 = off_e + bm * 128;

    int t = threadIdx.x;
    int warp = t >> 5, lane = t & 31;
    int wm = (warp & 1) * 64;      // warp M offset
    int wn = (warp >> 1) * 64;     // warp N offset

    const __half* A = (FFN1 ? g_Xg : g_Hg) + (size_t)slot0 * KSTRIDE + k_base;
    const __half* B = (FFN1 ? g_W1t : g_W2t) + ((size_t)e * NTOT + n_base) * KSTRIDE + k_base;
    const float* bias = bias_all + (size_t)e * NTOT;

    auto load_stage = [&](int stage, int ch) {
        uint32_t sb = smb + stage * STAGEB;
        int k0 = ch * 32;
        #pragma unroll
        for (int rep = 0; rep < 4; rep++) {
            int i = t + rep * 128;                 // 0..511
            int row = i >> 2, c = i & 3;
            uint32_t d = (uint32_t)(row * ROWB + c * 16);
            size_t src = (size_t)row * KSTRIDE + k0 + c * 8;
            cp16(sb + T_A + d, A + src);
            cp16(sb + T_B + d, B + src);
        }
    };

    load_stage(0, 0); CP_COMMIT();
    load_stage(1, 1); CP_COMMIT();
    load_stage(2, 2); CP_COMMIT();

    float acc[4][8][4];
    #pragma unroll
    for (int mt = 0; mt < 4; mt++)
        #pragma unroll
        for (int nt = 0; nt < 8; nt++)
            #pragma unroll
            for (int i = 0; i < 4; i++) acc[mt][nt][i] = 0.f;

    int g = lane >> 3, r8 = lane & 7;
    uint32_t aRow = (uint32_t)(wm + r8 + (g & 1) * 8);
    uint32_t aK   = (uint32_t)((g >> 1) * 8);
    uint32_t bRow = (uint32_t)(wn + r8 + (g >> 1) * 8);
    uint32_t bK   = (uint32_t)((g & 1) * 8);

    for (int ch = 0; ch < NCHUNK; ch++) {
        CP_WAIT2();
        __syncthreads();      // single barrier per chunk
        if (ch + 3 < NCHUNK) load_stage((ch + 3) % NSTAGE, ch + 3);
        CP_COMMIT();

        uint32_t sb = smb + (ch % NSTAGE) * STAGEB;
        #pragma unroll
        for (int kc = 0; kc < 2; kc++) {
            uint32_t af[4][4];
            #pragma unroll
            for (int mt = 0; mt < 4; mt++) {
                uint32_t ad = sb + (aRow + mt * 16) * ROWB + (kc * 16 + aK) * 2;
                ldm4(af[mt], ad + T_A);
            }
            uint32_t bf[4][4];
            #pragma unroll
            for (int np = 0; np < 4; np++) {
                uint32_t bd = sb + (bRow + np * 16) * ROWB + (kc * 16 + bK) * 2;
                ldm4(bf[np], bd + T_B);
            }
            #pragma unroll
            for (int mt = 0; mt < 4; mt++)
                #pragma unroll
                for (int nt = 0; nt < 8; nt++)
                    mma16816(acc[mt][nt], af[mt], &bf[nt >> 1][(nt & 1) * 2]);
        }
    }

    // epilogue
    int rlo = lane >> 2;            // 0..7
    int cpair = (lane & 3) * 2;     // 0,2,4,6
    #pragma unroll
    for (int mt = 0; mt < 4; mt++) {
        #pragma unroll
        for (int half = 0; half < 2; half++) {
            int m = bm * 128 + wm + mt * 16 + half * 8 + rlo;
            if (m >= cnt) continue;
            int slot = off_e + m;
            if (FFN1) {
                #pragma unroll
                for (int nt = 0; nt < 8; nt++) {
                    int col = n_base + wn + nt * 8 + cpair;
                    float v0 = acc[mt][nt][half * 2]     + bias[col];
                    float v1 = acc[mt][nt][half * 2 + 1] + bias[col + 1];
                    v0 = fmaxf(v0, 0.f); v1 = fmaxf(v1, 0.f);
                    size_t o = (size_t)slot * HID + col;
                    *(uint32_t*)(g_Hg + o) =
                        pack2h(__float2half_rn(v0), __float2half_rn(v1));
                }
            } else {
                int token = g_slot_token[slot];
                float w = g_slot_w[slot];
                float* orow = out + (size_t)token * DIM;
                bool add_bias = (ks == 0);
                #pragma unroll
                for (int nt = 0; nt < 8; nt++) {
                    int col = n_base + wn + nt * 8 + cpair;
                    float b0 = add_bias ? bias[col]     : 0.f;
                    float b1 = add_bias ? bias[col + 1] : 0.f;
                    float v0 = acc[mt][nt][half * 2]     + b0;
                    float v1 = acc[mt][nt][half * 2 + 1] + b1;
                    atomicAdd(orow + col,     w * v0);
                    atomicAdd(orow + col + 1, w * v1);
                }
            }
        }
    }
}

// ---------------- launch (fork/join: side stream does memset + weight prep) ----------------
extern "C" void kernel_launch(void* const* d_in, const int* in_sizes, int n_in,
                              void* d_out, int out_size) {
    const float* x  = (const float*)d_in[0];
    const float* Wg = (const float*)d_in[1];
    const float* bg = (const float*)d_in[2];
    const float* W1 = (const float*)d_in[3];
    const float* b1 = (const float*)d_in[4];
    const float* W2 = (const float*)d_in[5];
    const float* b2 = (const float*)d_in[6];
    float* out = (float*)d_out;

    static cudaStream_t s2 = []() {
        cudaStream_t s; cudaStreamCreateWithFlags(&s, cudaStreamNonBlocking); return s;
    }();
    static cudaEvent_t evF = []() {
        cudaEvent_t e; cudaEventCreateWithFlags(&e, cudaEventDisableTiming); return e;
    }();
    static cudaEvent_t ev1 = []() {
        cudaEvent_t e; cudaEventCreateWithFlags(&e, cudaEventDisableTiming); return e;
    }();
    static cudaEvent_t ev2 = []() {
        cudaEvent_t e; cudaEventCreateWithFlags(&e, cudaEventDisableTiming); return e;
    }();

    cudaFuncSetAttribute((const void*)k_gemm<DIM, DIM, true>,
                         cudaFuncAttributeMaxDynamicSharedMemorySize, SMEM_BYTES);
    cudaFuncSetAttribute((const void*)k_gemm<HID, DIM, false>,
                         cudaFuncAttributeMaxDynamicSharedMemorySize, SMEM_BYTES);

    // fork: memset(out) + weight prep on side stream (no routing deps)
    cudaEventRecord(evF, 0);
    cudaStreamWaitEvent(s2, evF, 0);
    k_zero_out<<<(N_TOK * DIM / 4) / 256, 256, 0, s2>>>(out);
    k_prep_w<<<dim3(HID / 32, DIM / 64, NEXP), dim3(32, 8), 0, s2>>>(W1, DIM, HID, 0);
    cudaEventRecord(ev1, s2);
    k_prep_w<<<dim3(DIM / 32, HID / 64, NEXP), dim3(32, 8), 0, s2>>>(W2, HID, DIM, 1);
    cudaEventRecord(ev2, s2);

    // main branch: routing
    k_gate<<<N_TOK / 8, 256>>>(x, Wg, bg);
    k_scanscatter<<<1, 256>>>();
    k_gather<<<NSLOT, 128>>>(x);

    // join W1, then GEMM1 (K=1024, no split)
    cudaStreamWaitEvent(0, ev1, 0);
    k_gemm<DIM, DIM, true><<<dim3(HID / 128, MAX_TILES, 1), 128, SMEM_BYTES>>>(b1, out);
    // join W2 (+ memset), then GEMM2 with 4-way k-split (fused combine via atomics)
    cudaStreamWaitEvent(0, ev2, 0);
    k_gemm<HID, DIM, false><<<dim3(DIM / 128, MAX_TILES, 4), 128, SMEM_BYTES>>>(b2, out);
}

// round 14
// speedup vs baseline: 1.0854x; 1.0854x over previous
#include <cuda_runtime.h>
#include <cuda_fp16.h>
#include <stdint.h>
#include <math.h>

#define N_TOK 4096
#define DIM   1024
#define HID   4096
#define NEXP  8
#define NSLOT 8192
#define SLOT_PAD (NSLOT + 128)
#define MAX_TILES 72

// ---------------- scratch (__device__ globals only) ----------------
__device__ int g_offsets[NEXP + 1];
__device__ int g_tg_e[N_TOK * 2];
__device__ float g_tg_w[N_TOK * 2];
__device__ int g_slot_token[NSLOT];
__device__ float g_slot_w[NSLOT];
__device__ int g_tile_e[MAX_TILES];
__device__ int g_tile_bm[MAX_TILES];
__device__ int g_ntiles;

__device__ __align__(16) __half g_Xg[(size_t)SLOT_PAD * DIM];
__device__ __align__(16) __half g_Hg[(size_t)SLOT_PAD * HID];
__device__ __align__(16) __half g_W1t[(size_t)NEXP * HID * DIM]; // [e][h][d]
__device__ __align__(16) __half g_W2t[(size_t)NEXP * DIM * HID]; // [e][d][h]

// ---------------- helpers ----------------
__device__ __forceinline__ uint32_t smem_u32(const void* p) {
    uint32_t a;
    asm("{ .reg .u64 t; cvta.to.shared.u64 t, %1; cvt.u32.u64 %0, t; }" : "=r"(a) : "l"(p));
    return a;
}
__device__ __forceinline__ uint32_t pack2h(__half a, __half b) {
    return (uint32_t)__half_as_ushort(a) | ((uint32_t)__half_as_ushort(b) << 16);
}
__device__ __forceinline__ void cp16(uint32_t dst, const void* src) {
    asm volatile("cp.async.cg.shared.global [%0], [%1], 16;" :: "r"(dst), "l"(src));
}
#define CP_COMMIT() asm volatile("cp.async.commit_group;" ::: "memory")
#define CP_WAIT2()  asm volatile("cp.async.wait_group 2;" ::: "memory")

__device__ __forceinline__ void ldm4(uint32_t* r, uint32_t addr) {
    asm volatile("ldmatrix.sync.aligned.m8n8.x4.shared.b16 {%0,%1,%2,%3}, [%4];"
                 : "=r"(r[0]), "=r"(r[1]), "=r"(r[2]), "=r"(r[3]) : "r"(addr));
}
__device__ __forceinline__ void mma16816(float* c, const uint32_t* a, const uint32_t* b) {
    asm volatile("mma.sync.aligned.m16n8k16.row.col.f32.f16.f16.f32 "
                 "{%0,%1,%2,%3}, {%4,%5,%6,%7}, {%8,%9}, {%0,%1,%2,%3};"
                 : "+f"(c[0]), "+f"(c[1]), "+f"(c[2]), "+f"(c[3])
                 : "r"(a[0]), "r"(a[1]), "r"(a[2]), "r"(a[3]), "r"(b[0]), "r"(b[1]));
}

// ---------------- 0) zero out ----------------
__global__ void k_zero_out(float* __restrict__ out) {
    int i = blockIdx.x * blockDim.x + threadIdx.x;
    ((float4*)out)[i] = make_float4(0.f, 0.f, 0.f, 0.f);
}

// ---------------- 1) gating (Wg staged in smem once per block) ----------------
__global__ void k_gate(const float* __restrict__ x, const float* __restrict__ Wg,
                       const float* __restrict__ bg) {
    __shared__ float4 s_wg[DIM * 2];     // 1024 rows x 8 experts = 2 float4 per row
    int tid = threadIdx.x;
    for (int i = tid; i < DIM * 2; i += 256)
        s_wg[i] = ((const float4*)Wg)[i];
    __syncthreads();

    int wid = tid >> 5, lane = tid & 31;
    int n = blockIdx.x * 8 + wid;
    float acc[8] = {0,0,0,0,0,0,0,0};
    for (int k = lane; k < DIM; k += 32) {
        float xv = x[(size_t)n * DIM + k];
        float4 w0 = s_wg[k * 2], w1 = s_wg[k * 2 + 1];
        acc[0] = fmaf(xv, w0.x, acc[0]); acc[1] = fmaf(xv, w0.y, acc[1]);
        acc[2] = fmaf(xv, w0.z, acc[2]); acc[3] = fmaf(xv, w0.w, acc[3]);
        acc[4] = fmaf(xv, w1.x, acc[4]); acc[5] = fmaf(xv, w1.y, acc[5]);
        acc[6] = fmaf(xv, w1.z, acc[6]); acc[7] = fmaf(xv, w1.w, acc[7]);
    }
    #pragma unroll
    for (int e = 0; e < 8; e++)
        #pragma unroll
        for (int off = 16; off; off >>= 1)
            acc[e] += __shfl_down_sync(0xffffffffu, acc[e], off);
    if (lane == 0) {
        float s[8];
        #pragma unroll
        for (int e = 0; e < 8; e++) s[e] = acc[e] + bg[e];
        int e0 = 0; float s0 = s[0];
        #pragma unroll
        for (int e = 1; e < 8; e++) if (s[e] > s0) { s0 = s[e]; e0 = e; }
        int e1 = -1; float s1 = -3.0e38f;
        #pragma unroll
        for (int e = 0; e < 8; e++) if (e != e0 && s[e] > s1) { s1 = s[e]; e1 = e; }
        float t = expf(s1 - s0);
        g_tg_e[n * 2] = e0; g_tg_e[n * 2 + 1] = e1;
        g_tg_w[n * 2] = 1.f / (1.f + t); g_tg_w[n * 2 + 1] = t / (1.f + t);
    }
}

// ---------------- 1b) fused scan + tile map + scatter (single block) ----------------
__global__ void k_scanscatter() {
    __shared__ int cnt[NEXP], off[NEXP], cur[NEXP];
    int t = threadIdx.x;
    if (t < NEXP) cnt[t] = 0;
    __syncthreads();
    for (int i = t; i < N_TOK * 2; i += 256) atomicAdd(&cnt[g_tg_e[i]], 1);
    __syncthreads();
    if (t == 0) {
        int o = 0, tt = 0;
        for (int e = 0; e < NEXP; e++) {
            off[e] = o; g_offsets[e] = o; cur[e] = 0;
            int c = cnt[e];
            for (int bm = 0; bm * 128 < c; bm++) { g_tile_e[tt] = e; g_tile_bm[tt] = bm; tt++; }
            o += c;
        }
        g_offsets[NEXP] = o;
        g_ntiles = tt;
    }
    __syncthreads();
    for (int i = t; i < N_TOK * 2; i += 256) {
        int e = g_tg_e[i];
        int slot = off[e] + atomicAdd(&cur[e], 1);
        g_slot_token[slot] = i >> 1;
        g_slot_w[slot] = g_tg_w[i];
    }
}

// ---------------- 2) gather x -> fp16 ----------------
__global__ void k_gather(const float* __restrict__ x) {
    int s = blockIdx.x, t = threadIdx.x;
    int n = g_slot_token[s];
    const float4* xr = (const float4*)(x + (size_t)n * DIM);
    float4 a = xr[t * 2], b = xr[t * 2 + 1];
    uint32_t p[4];
    p[0] = pack2h(__float2half_rn(a.x), __float2half_rn(a.y));
    p[1] = pack2h(__float2half_rn(a.z), __float2half_rn(a.w));
    p[2] = pack2h(__float2half_rn(b.x), __float2half_rn(b.y));
    p[3] = pack2h(__float2half_rn(b.z), __float2half_rn(b.w));
    *(uint4*)(g_Xg + (size_t)s * DIM + t * 8) = *(uint4*)p;
}

// ---------------- 3) weight transpose to fp16: in[e][R][C] -> out[e][C][R] ----------------
__global__ void k_prep_w(const float* __restrict__ in, int R, int C, int which) {
    __half* o = which ? g_W2t : g_W1t;
    __shared__ float tile[32][65];   // [c][r]
    int e = blockIdx.z;
    int r0 = blockIdx.y * 64, c0 = blockIdx.x * 32;
    int tx = threadIdx.x, ty = threadIdx.y;   // 32 x 8
    const float* ip = in + (size_t)e * R * C;
    #pragma unroll
    for (int j = 0; j < 64; j += 8)
        tile[tx][ty + j] = ip[(size_t)(r0 + ty + j) * C + c0 + tx];
    __syncthreads();
    size_t ob = (size_t)e * R * C;
    int t = ty * 32 + tx;
    #pragma unroll
    for (int i = t; i < 1024; i += 256) {
        int c = i >> 5;            // 0..31
        int rp = (i & 31) * 2;     // 0..62
        uint32_t v = pack2h(__float2half_rn(tile[c][rp]),
                            __float2half_rn(tile[c][rp + 1]));
        *(uint32_t*)(o + ob + (size_t)(c0 + c) * R + r0 + rp) = v;
    }
}

// ---------------- 4) grouped GEMM: 128x128x32 CTA, 4 warps 64x64, 4-stage ----------------
#define ROWB   80
#define T_A    0
#define T_B    10240
#define STAGEB 20480
#define NSTAGE 4
#define SMEM_BYTES (STAGEB * NSTAGE)

template <int KDIM, bool FFN1>
__global__ void __launch_bounds__(128) k_gemm(const float* __restrict__ bias_all,
                                              float* __restrict__ out) {
    constexpr int NTOT = FFN1 ? HID : DIM;
    constexpr int NCHUNK = KDIM / 32;
    extern __shared__ char sm[];
    uint32_t smb = smem_u32(sm);

    int tile = blockIdx.y;
    if (tile >= g_ntiles) return;
    int e = g_tile_e[tile];
    int bm = g_tile_bm[tile];
    int off_e = g_offsets[e];
    int cnt = g_offsets[e + 1] - off_e;
    int n_base = blockIdx.x * 128;
    int slot0 = off_e + bm * 128;

    int t = threadIdx.x;
    int warp = t >> 5, lane = t & 31;
    int wm = (warp & 1) * 64;      // warp M offset
    int wn = (warp >> 1) * 64;     // warp N offset

    const __half* A = (FFN1 ? g_Xg : g_Hg) + (size_t)slot0 * KDIM;
    const __half* B = (FFN1 ? g_W1t : g_W2t) + ((size_t)e * NTOT + n_base) * KDIM;
    const float* bias = bias_all + (size_t)e * NTOT;

    auto load_stage = [&](int stage, int ch) {
        uint32_t sb = smb + stage * STAGEB;
        int k0 = ch * 32;
        #pragma unroll
        for (int rep = 0; rep < 4; rep++) {
            int i = t + rep * 128;                 // 0..511
            int row = i >> 2, c = i & 3;
            uint32_t d = (uint32_t)(row * ROWB + c * 16);
            size_t src = (size_t)row * KDIM + k0 + c * 8;
            cp16(sb + T_A + d, A + src);
            cp16(sb + T_B + d, B + src);
        }
    };

    load_stage(0, 0); CP_COMMIT();
    load_stage(1, 1); CP_COMMIT();
    load_stage(2, 2); CP_COMMIT();

    float acc[4][8][4];
    #pragma unroll
    for (int mt = 0; mt < 4; mt++)
        #pragma unroll
        for (int nt = 0; nt < 8; nt++)
            #pragma unroll
            for (int i = 0; i < 4; i++) acc[mt][nt][i] = 0.f;

    int g = lane >> 3, r8 = lane & 7;
    uint32_t aRow = (uint32_t)(wm + r8 + (g & 1) * 8);
    uint32_t aK   = (uint32_t)((g >> 1) * 8);
    uint32_t bRow = (uint32_t)(wn + r8 + (g >> 1) * 8);
    uint32_t bK   = (uint32_t)((g & 1) * 8);

    for (int ch = 0; ch < NCHUNK; ch++) {
        CP_WAIT2();
        __syncthreads();      // single barrier per chunk
        if (ch + 3 < NCHUNK) load_stage((ch + 3) % NSTAGE, ch + 3);
        CP_COMMIT();

        uint32_t sb = smb + (ch % NSTAGE) * STAGEB;
        #pragma unroll
        for (int kc = 0; kc < 2; kc++) {
            uint32_t af[4][4];
            #pragma unroll
            for (int mt = 0; mt < 4; mt++) {
                uint32_t ad = sb + (aRow + mt * 16) * ROWB + (kc * 16 + aK) * 2;
                ldm4(af[mt], ad + T_A);
            }
            uint32_t bf[4][4];
            #pragma unroll
            for (int np = 0; np < 4; np++) {
                uint32_t bd = sb + (bRow + np * 16) * ROWB + (kc * 16 + bK) * 2;
                ldm4(bf[np], bd + T_B);
            }
            #pragma unroll
            for (int mt = 0; mt < 4; mt++)
                #pragma unroll
                for (int nt = 0; nt < 8; nt++)
                    mma16816(acc[mt][nt], af[mt], &bf[nt >> 1][(nt & 1) * 2]);
        }
    }

    // epilogue
    int rlo = lane >> 2;            // 0..7
    int cpair = (lane & 3) * 2;     // 0,2,4,6
    #pragma unroll
    for (int mt = 0; mt < 4; mt++) {
        #pragma unroll
        for (int half = 0; half < 2; half++) {
            int m = bm * 128 + wm + mt * 16 + half * 8 + rlo;
            if (m >= cnt) continue;
            int slot = off_e + m;
            if (FFN1) {
                #pragma unroll
                for (int nt = 0; nt < 8; nt++) {
                    int col = n_base + wn + nt * 8 + cpair;
                    float v0 = acc[mt][nt][half * 2]     + bias[col];
                    float v1 = acc[mt][nt][half * 2 + 1] + bias[col + 1];
                    v0 = fmaxf(v0, 0.f); v1 = fmaxf(v1, 0.f);
                    size_t o = (size_t)slot * HID + col;
                    *(uint32_t*)(g_Hg + o) =
                        pack2h(__float2half_rn(v0), __float2half_rn(v1));
                }
            } else {
                int token = g_slot_token[slot];
                float w = g_slot_w[slot];
                float* orow = out + (size_t)token * DIM;
                #pragma unroll
                for (int nt = 0; nt < 8; nt++) {
                    int col = n_base + wn + nt * 8 + cpair;
                    float v0 = acc[mt][nt][half * 2]     + bias[col];
                    float v1 = acc[mt][nt][half * 2 + 1] + bias[col + 1];
                    atomicAdd(orow + col,     w * v0);
                    atomicAdd(orow + col + 1, w * v1);
                }
            }
        }
    }
}

// ---------------- launch (fork/join: side stream does memset + weight prep) ----------------
extern "C" void kernel_launch(void* const* d_in, const int* in_sizes, int n_in,
                              void* d_out, int out_size) {
    const float* x  = (const float*)d_in[0];
    const float* Wg = (const float*)d_in[1];
    const float* bg = (const float*)d_in[2];
    const float* W1 = (const float*)d_in[3];
    const float* b1 = (const float*)d_in[4];
    const float* W2 = (const float*)d_in[5];
    const float* b2 = (const float*)d_in[6];
    float* out = (float*)d_out;

    static cudaStream_t s2 = []() {
        cudaStream_t s; cudaStreamCreateWithFlags(&s, cudaStreamNonBlocking); return s;
    }();
    static cudaEvent_t evF = []() {
        cudaEvent_t e; cudaEventCreateWithFlags(&e, cudaEventDisableTiming); return e;
    }();
    static cudaEvent_t ev1 = []() {
        cudaEvent_t e; cudaEventCreateWithFlags(&e, cudaEventDisableTiming); return e;
    }();
    static cudaEvent_t ev2 = []() {
        cudaEvent_t e; cudaEventCreateWithFlags(&e, cudaEventDisableTiming); return e;
    }();

    cudaFuncSetAttribute(k_gemm<DIM, true>,  cudaFuncAttributeMaxDynamicSharedMemorySize, SMEM_BYTES);
    cudaFuncSetAttribute(k_gemm<HID, false>, cudaFuncAttributeMaxDynamicSharedMemorySize, SMEM_BYTES);

    // fork: memset(out) + weight prep on side stream (no routing deps)
    cudaEventRecord(evF, 0);
    cudaStreamWaitEvent(s2, evF, 0);
    k_zero_out<<<(N_TOK * DIM / 4) / 256, 256, 0, s2>>>(out);
    k_prep_w<<<dim3(HID / 32, DIM / 64, NEXP), dim3(32, 8), 0, s2>>>(W1, DIM, HID, 0);
    cudaEventRecord(ev1, s2);
    k_prep_w<<<dim3(DIM / 32, HID / 64, NEXP), dim3(32, 8), 0, s2>>>(W2, HID, DIM, 1);
    cudaEventRecord(ev2, s2);

    // main branch: routing
    k_gate<<<N_TOK / 8, 256>>>(x, Wg, bg);
    k_scanscatter<<<1, 256>>>();
    k_gather<<<NSLOT, 128>>>(x);

    // join W1, then GEMM1
    cudaStreamWaitEvent(0, ev1, 0);
    k_gemm<DIM, true><<<dim3(HID / 128, MAX_TILES), 128, SMEM_BYTES>>>(b1, out);
    // join W2 (+ memset), then GEMM2 (fused combine via atomics)
    cudaStreamWaitEvent(0, ev2, 0);
    k_gemm<HID, false><<<dim3(DIM / 128, MAX_TILES), 128, SMEM_BYTES>>>(b2, out);
}

// round 15
// speedup vs baseline: 1.0892x; 1.0034x over previous
#include <cuda_runtime.h>
#include <cuda_fp16.h>
#include <stdint.h>
#include <math.h>

#define N_TOK 4096
#define DIM   1024
#define HID   4096
#define NEXP  8
#define NSLOT 8192
#define SLOT_PAD (NSLOT + 128)
#define MAX_TILES 72

// ---------------- scratch (__device__ globals only) ----------------
__device__ int g_offsets[NEXP + 1];
__device__ int g_tg_e[N_TOK * 2];
__device__ float g_tg_w[N_TOK * 2];
__device__ int g_slot_token[NSLOT];
__device__ float g_slot_w[NSLOT];
__device__ int g_tile_e[MAX_TILES];
__device__ int g_tile_bm[MAX_TILES];
__device__ int g_ntiles;

__device__ __align__(16) __half g_Xg[(size_t)SLOT_PAD * DIM];
__device__ __align__(16) __half g_Hg[(size_t)SLOT_PAD * HID];
__device__ __align__(16) __half g_W1t[(size_t)NEXP * HID * DIM]; // [e][h][d]
__device__ __align__(16) __half g_W2t[(size_t)NEXP * DIM * HID]; // [e][d][h]

// ---------------- helpers ----------------
__device__ __forceinline__ uint32_t smem_u32(const void* p) {
    uint32_t a;
    asm("{ .reg .u64 t; cvta.to.shared.u64 t, %1; cvt.u32.u64 %0, t; }" : "=r"(a) : "l"(p));
    return a;
}
__device__ __forceinline__ uint32_t pack2h(__half a, __half b) {
    return (uint32_t)__half_as_ushort(a) | ((uint32_t)__half_as_ushort(b) << 16);
}
__device__ __forceinline__ void cp16(uint32_t dst, const void* src) {
    asm volatile("cp.async.cg.shared.global [%0], [%1], 16;" :: "r"(dst), "l"(src));
}
#define CP_COMMIT() asm volatile("cp.async.commit_group;" ::: "memory")
#define CP_WAIT2()  asm volatile("cp.async.wait_group 2;" ::: "memory")

__device__ __forceinline__ void ldm4(uint32_t* r, uint32_t addr) {
    asm volatile("ldmatrix.sync.aligned.m8n8.x4.shared.b16 {%0,%1,%2,%3}, [%4];"
                 : "=r"(r[0]), "=r"(r[1]), "=r"(r[2]), "=r"(r[3]) : "r"(addr));
}
__device__ __forceinline__ void mma16816(float* c, const uint32_t* a, const uint32_t* b) {
    asm volatile("mma.sync.aligned.m16n8k16.row.col.f32.f16.f16.f32 "
                 "{%0,%1,%2,%3}, {%4,%5,%6,%7}, {%8,%9}, {%0,%1,%2,%3};"
                 : "+f"(c[0]), "+f"(c[1]), "+f"(c[2]), "+f"(c[3])
                 : "r"(a[0]), "r"(a[1]), "r"(a[2]), "r"(a[3]), "r"(b[0]), "r"(b[1]));
}

// ---------------- 0) zero out ----------------
__global__ void k_zero_out(float* __restrict__ out) {
    int i = blockIdx.x * blockDim.x + threadIdx.x;
    ((float4*)out)[i] = make_float4(0.f, 0.f, 0.f, 0.f);
}

// ---------------- 1) gating ----------------
__global__ void k_gate(const float* __restrict__ x, const float* __restrict__ Wg,
                       const float* __restrict__ bg) {
    int wid = threadIdx.x >> 5, lane = threadIdx.x & 31;
    int n = blockIdx.x * 8 + wid;
    float acc[8] = {0,0,0,0,0,0,0,0};
    const float4* wg4 = (const float4*)Wg;
    for (int k = lane; k < DIM; k += 32) {
        float xv = x[(size_t)n * DIM + k];
        float4 w0 = wg4[k * 2], w1 = wg4[k * 2 + 1];
        acc[0] = fmaf(xv, w0.x, acc[0]); acc[1] = fmaf(xv, w0.y, acc[1]);
        acc[2] = fmaf(xv, w0.z, acc[2]); acc[3] = fmaf(xv, w0.w, acc[3]);
        acc[4] = fmaf(xv, w1.x, acc[4]); acc[5] = fmaf(xv, w1.y, acc[5]);
        acc[6] = fmaf(xv, w1.z, acc[6]); acc[7] = fmaf(xv, w1.w, acc[7]);
    }
    #pragma unroll
    for (int e = 0; e < 8; e++)
        #pragma unroll
        for (int off = 16; off; off >>= 1)
            acc[e] += __shfl_down_sync(0xffffffffu, acc[e], off);
    if (lane == 0) {
        float s[8];
        #pragma unroll
        for (int e = 0; e < 8; e++) s[e] = acc[e] + bg[e];
        int e0 = 0; float s0 = s[0];
        #pragma unroll
        for (int e = 1; e < 8; e++) if (s[e] > s0) { s0 = s[e]; e0 = e; }
        int e1 = -1; float s1 = -3.0e38f;
        #pragma unroll
        for (int e = 0; e < 8; e++) if (e != e0 && s[e] > s1) { s1 = s[e]; e1 = e; }
        float t = expf(s1 - s0);
        g_tg_e[n * 2] = e0; g_tg_e[n * 2 + 1] = e1;
        g_tg_w[n * 2] = 1.f / (1.f + t); g_tg_w[n * 2 + 1] = t / (1.f + t);
    }
}

// ---------------- 1b) fused scan + tile map + scatter (single block) ----------------
__global__ void k_scanscatter() {
    __shared__ int cnt[NEXP], off[NEXP], cur[NEXP];
    int t = threadIdx.x;
    if (t < NEXP) cnt[t] = 0;
    __syncthreads();
    for (int i = t; i < N_TOK * 2; i += 256) atomicAdd(&cnt[g_tg_e[i]], 1);
    __syncthreads();
    if (t == 0) {
        int o = 0, tt = 0;
        for (int e = 0; e < NEXP; e++) {
            off[e] = o; g_offsets[e] = o; cur[e] = 0;
            int c = cnt[e];
            for (int bm = 0; bm * 128 < c; bm++) { g_tile_e[tt] = e; g_tile_bm[tt] = bm; tt++; }
            o += c;
        }
        g_offsets[NEXP] = o;
        g_ntiles = tt;
    }
    __syncthreads();
    for (int i = t; i < N_TOK * 2; i += 256) {
        int e = g_tg_e[i];
        int slot = off[e] + atomicAdd(&cur[e], 1);
        g_slot_token[slot] = i >> 1;
        g_slot_w[slot] = g_tg_w[i];
    }
}

// ---------------- 2) gather x -> fp16 ----------------
__global__ void k_gather(const float* __restrict__ x) {
    int s = blockIdx.x, t = threadIdx.x;
    int n = g_slot_token[s];
    const float4* xr = (const float4*)(x + (size_t)n * DIM);
    float4 a = xr[t * 2], b = xr[t * 2 + 1];
    uint32_t p[4];
    p[0] = pack2h(__float2half_rn(a.x), __float2half_rn(a.y));
    p[1] = pack2h(__float2half_rn(a.z), __float2half_rn(a.w));
    p[2] = pack2h(__float2half_rn(b.x), __float2half_rn(b.y));
    p[3] = pack2h(__float2half_rn(b.z), __float2half_rn(b.w));
    *(uint4*)(g_Xg + (size_t)s * DIM + t * 8) = *(uint4*)p;
}

// ---------------- 3) weight transpose to fp16: in[e][R][C] -> out[e][C][R] ----------------
__global__ void k_prep_w(const float* __restrict__ in, int R, int C, int which) {
    __half* o = which ? g_W2t : g_W1t;
    __shared__ float tile[32][65];   // [c][r]
    int e = blockIdx.z;
    int r0 = blockIdx.y * 64, c0 = blockIdx.x * 32;
    int tx = threadIdx.x, ty = threadIdx.y;   // 32 x 8
    const float* ip = in + (size_t)e * R * C;
    #pragma unroll
    for (int j = 0; j < 64; j += 8)
        tile[tx][ty + j] = ip[(size_t)(r0 + ty + j) * C + c0 + tx];
    __syncthreads();
    size_t ob = (size_t)e * R * C;
    int t = ty * 32 + tx;
    #pragma unroll
    for (int i = t; i < 1024; i += 256) {
        int c = i >> 5;            // 0..31
        int rp = (i & 31) * 2;     // 0..62
        uint32_t v = pack2h(__float2half_rn(tile[c][rp]),
                            __float2half_rn(tile[c][rp + 1]));
        *(uint32_t*)(o + ob + (size_t)(c0 + c) * R + r0 + rp) = v;
    }
}

// ---------------- 4) grouped GEMM: 128x128x32 CTA, 4 warps 64x64, 4-stage ----------------
#define ROWB   80
#define T_A    0
#define T_B    10240
#define STAGEB 20480
#define NSTAGE 4
#define SMEM_BYTES (STAGEB * NSTAGE)

template <int KDIM, bool FFN1>
__global__ void __launch_bounds__(128) k_gemm(const float* __restrict__ bias_all,
                                              float* __restrict__ out) {
    constexpr int NTOT = FFN1 ? HID : DIM;
    constexpr int NCHUNK = KDIM / 32;
    extern __shared__ char sm[];
    uint32_t smb = smem_u32(sm);

    int tile = blockIdx.y;
    if (tile >= g_ntiles) return;
    int e = g_tile_e[tile];
    int bm = g_tile_bm[tile];
    int off_e = g_offsets[e];
    int cnt = g_offsets[e + 1] - off_e;
    int n_base = blockIdx.x * 128;
    int slot0 = off_e + bm * 128;

    int t = threadIdx.x;
    int warp = t >> 5, lane = t & 31;
    int wm = (warp & 1) * 64;      // warp M offset
    int wn = (warp >> 1) * 64;     // warp N offset

    const __half* A = (FFN1 ? g_Xg : g_Hg) + (size_t)slot0 * KDIM;
    const __half* B = (FFN1 ? g_W1t : g_W2t) + ((size_t)e * NTOT + n_base) * KDIM;
    const float* bias = bias_all + (size_t)e * NTOT;

    auto load_stage = [&](int stage, int ch) {
        uint32_t sb = smb + stage * STAGEB;
        int k0 = ch * 32;
        #pragma unroll
        for (int rep = 0; rep < 4; rep++) {
            int i = t + rep * 128;                 // 0..511
            int row = i >> 2, c = i & 3;
            uint32_t d = (uint32_t)(row * ROWB + c * 16);
            size_t src = (size_t)row * KDIM + k0 + c * 8;
            cp16(sb + T_A + d, A + src);
            cp16(sb + T_B + d, B + src);
        }
    };

    load_stage(0, 0); CP_COMMIT();
    load_stage(1, 1); CP_COMMIT();
    load_stage(2, 2); CP_COMMIT();

    float acc[4][8][4];
    #pragma unroll
    for (int mt = 0; mt < 4; mt++)
        #pragma unroll
        for (int nt = 0; nt < 8; nt++)
            #pragma unroll
            for (int i = 0; i < 4; i++) acc[mt][nt][i] = 0.f;

    int g = lane >> 3, r8 = lane & 7;
    uint32_t aRow = (uint32_t)(wm + r8 + (g & 1) * 8);
    uint32_t aK   = (uint32_t)((g >> 1) * 8);
    uint32_t bRow = (uint32_t)(wn + r8 + (g >> 1) * 8);
    uint32_t bK   = (uint32_t)((g & 1) * 8);

    for (int ch = 0; ch < NCHUNK; ch++) {
        CP_WAIT2();
        __syncthreads();      // single barrier per chunk
        if (ch + 3 < NCHUNK) load_stage((ch + 3) % NSTAGE, ch + 3);
        CP_COMMIT();

        uint32_t sb = smb + (ch % NSTAGE) * STAGEB;
        #pragma unroll
        for (int kc = 0; kc < 2; kc++) {
            uint32_t af[4][4];
            #pragma unroll
            for (int mt = 0; mt < 4; mt++) {
                uint32_t ad = sb + (aRow + mt * 16) * ROWB + (kc * 16 + aK) * 2;
                ldm4(af[mt], ad + T_A);
            }
            uint32_t bf[4][4];
            #pragma unroll
            for (int np = 0; np < 4; np++) {
                uint32_t bd = sb + (bRow + np * 16) * ROWB + (kc * 16 + bK) * 2;
                ldm4(bf[np], bd + T_B);
            }
            #pragma unroll
            for (int mt = 0; mt < 4; mt++)
                #pragma unroll
                for (int nt = 0; nt < 8; nt++)
                    mma16816(acc[mt][nt], af[mt], &bf[nt >> 1][(nt & 1) * 2]);
        }
    }

    // epilogue
    int rlo = lane >> 2;            // 0..7
    int cpair = (lane & 3) * 2;     // 0,2,4,6
    #pragma unroll
    for (int mt = 0; mt < 4; mt++) {
        #pragma unroll
        for (int half = 0; half < 2; half++) {
            int m = bm * 128 + wm + mt * 16 + half * 8 + rlo;
            if (m >= cnt) continue;
            int slot = off_e + m;
            if (FFN1) {
                #pragma unroll
                for (int nt = 0; nt < 8; nt++) {
                    int col = n_base + wn + nt * 8 + cpair;
                    float v0 = acc[mt][nt][half * 2]     + bias[col];
                    float v1 = acc[mt][nt][half * 2 + 1] + bias[col + 1];
                    v0 = fmaxf(v0, 0.f); v1 = fmaxf(v1, 0.f);
                    size_t o = (size_t)slot * HID + col;
                    *(uint32_t*)(g_Hg + o) =
                        pack2h(__float2half_rn(v0), __float2half_rn(v1));
                }
            } else {
                int token = g_slot_token[slot];
                float w = g_slot_w[slot];
                float* orow = out + (size_t)token * DIM;
                #pragma unroll
                for (int nt = 0; nt < 8; nt++) {
                    int col = n_base + wn + nt * 8 + cpair;
                    float v0 = acc[mt][nt][half * 2]     + bias[col];
                    float v1 = acc[mt][nt][half * 2 + 1] + bias[col + 1];
                    atomicAdd(orow + col,     w * v0);
                    atomicAdd(orow + col + 1, w * v1);
                }
            }
        }
    }
}

// ---------------- launch (fork/join: side stream does memset + weight prep) ----------------
extern "C" void kernel_launch(void* const* d_in, const int* in_sizes, int n_in,
                              void* d_out, int out_size) {
    const float* x  = (const float*)d_in[0];
    const float* Wg = (const float*)d_in[1];
    const float* bg = (const float*)d_in[2];
    const float* W1 = (const float*)d_in[3];
    const float* b1 = (const float*)d_in[4];
    const float* W2 = (const float*)d_in[5];
    const float* b2 = (const float*)d_in[6];
    float* out = (float*)d_out;

    static cudaStream_t s2 = []() {
        cudaStream_t s; cudaStreamCreateWithFlags(&s, cudaStreamNonBlocking); return s;
    }();
    static cudaEvent_t evF = []() {
        cudaEvent_t e; cudaEventCreateWithFlags(&e, cudaEventDisableTiming); return e;
    }();
    static cudaEvent_t ev1 = []() {
        cudaEvent_t e; cudaEventCreateWithFlags(&e, cudaEventDisableTiming); return e;
    }();
    static cudaEvent_t ev2 = []() {
        cudaEvent_t e; cudaEventCreateWithFlags(&e, cudaEventDisableTiming); return e;
    }();

    cudaFuncSetAttribute(k_gemm<DIM, true>,  cudaFuncAttributeMaxDynamicSharedMemorySize, SMEM_BYTES);
    cudaFuncSetAttribute(k_gemm<HID, false>, cudaFuncAttributeMaxDynamicSharedMemorySize, SMEM_BYTES);

    // fork: memset(out) + weight prep on side stream (no routing deps)
    cudaEventRecord(evF, 0);
    cudaStreamWaitEvent(s2, evF, 0);
    k_zero_out<<<(N_TOK * DIM / 4) / 256, 256, 0, s2>>>(out);
    k_prep_w<<<dim3(HID / 32, DIM / 64, NEXP), dim3(32, 8), 0, s2>>>(W1, DIM, HID, 0);
    cudaEventRecord(ev1, s2);
    k_prep_w<<<dim3(DIM / 32, HID / 64, NEXP), dim3(32, 8), 0, s2>>>(W2, HID, DIM, 1);
    cudaEventRecord(ev2, s2);

    // main branch: routing
    k_gate<<<N_TOK / 8, 256>>>(x, Wg, bg);
    k_scanscatter<<<1, 256>>>();
    k_gather<<<NSLOT, 128>>>(x);

    // join W1, then GEMM1
    cudaStreamWaitEvent(0, ev1, 0);
    k_gemm<DIM, true><<<dim3(HID / 128, MAX_TILES), 128, SMEM_BYTES>>>(b1, out);
    // join W2 (+ memset), then GEMM2 (fused combine via atomics)
    cudaStreamWaitEvent(0, ev2, 0);
    k_gemm<HID, false><<<dim3(DIM / 128, MAX_TILES), 128, SMEM_BYTES>>>(b2, out);
}